// round 10
// baseline (speedup 1.0000x reference)
#include <cuda_runtime.h>
#include <cuda_fp16.h>
#include <math.h>
#include <stdint.h>

#define BB 4
#define NN 4096
#define DD 1024
#define HH 16
#define HDIM 64
#define GG 512
#define BNTOK (BB*NN)

// ---------------- scratch (device globals; no allocations allowed) ----------
__device__ float g_field[(size_t)BB * HH * GG * HDIM];  // 8MB (atomic-accumulated)

// fp16 operands (plain fp16: validated error budget, rel_err ~4e-4 vs 1e-3 gate)
__device__ __half g_x  [(size_t)BNTOK * DD];            // 32MB
__device__ __half g_wkv[(size_t)2048 * DD];             // 4MB  packed [k|v] per head
__device__ __half g_ow [(size_t)DD * DD];               // 2MB
__device__ __half g_A  [(size_t)BB * GG * DD];          // 4MB  conv result, repacked

// Replicates jnp: pos = (n/4095.0f)*511.0f ; int32 trunc ; clip
__device__ __forceinline__ int bin_of(int n) {
    float p = ((float)n / 4095.0f) * 511.0f;
    int g = (int)p;
    g = g < 0 ? 0 : g;
    return g > 511 ? 511 : g;
}

// ---------------- baseline-PTX tensor helpers (sm_80+, ok on compute_103) ---
__device__ __forceinline__ uint32_t smem_u32(const void* p) {
    uint32_t a;
    asm("{ .reg .u64 t; cvta.to.shared.u64 t, %1; cvt.u32.u64 %0, t; }" : "=r"(a) : "l"(p));
    return a;
}
__device__ __forceinline__ void ldmx4(uint32_t* r, uint32_t a) {
    asm volatile("ldmatrix.sync.aligned.m8n8.x4.shared.b16 {%0,%1,%2,%3}, [%4];"
        : "=r"(r[0]), "=r"(r[1]), "=r"(r[2]), "=r"(r[3]) : "r"(a));
}
__device__ __forceinline__ void mma16816(float* c, const uint32_t* a, const uint32_t* b) {
    asm volatile("mma.sync.aligned.m16n8k16.row.col.f32.f16.f16.f32 "
        "{%0,%1,%2,%3}, {%4,%5,%6,%7}, {%8,%9}, {%0,%1,%2,%3};"
        : "+f"(c[0]), "+f"(c[1]), "+f"(c[2]), "+f"(c[3])
        : "r"(a[0]), "r"(a[1]), "r"(a[2]), "r"(a[3]), "r"(b[0]), "r"(b[1]));
}
#define CP_ASYNC(d, s) asm volatile("cp.async.cg.shared.global [%0], [%1], 16;" :: "r"(d), "l"(s) : "memory")
#define CP_COMMIT()    asm volatile("cp.async.commit_group;" ::: "memory")
#define CP_WAIT1()     asm volatile("cp.async.wait_group 1;" ::: "memory")
#define CP_WAIT0()     asm volatile("cp.async.wait_group 0;" ::: "memory")

// Tiling: block 128x128, K chunk 64, 128B rows (Swizzle<3,4,3>).
// kv: 4 warps (2x2), warp tile 64x64; 2 stages x 32KB = 64KB -> 3 CTAs/SM.
// out: 8 warps (2x4), warp tile 64x32; 3 stages = 96KB -> 2 CTAs/SM.
#define KC       64
#define NCH      16                 // 1024 / 64
#define B_OFF    16384
#define STAGE    32768
#define KV_SMEM  (2*STAGE)          // 65536
#define OUT_SMEM (3*STAGE)          // 98304

// swizzled byte offset for (row, 16B-chunk c in 0..7)
__device__ __forceinline__ uint32_t swz(uint32_t row, uint32_t c) {
    return row * 128u + ((c ^ (row & 7u)) << 4);
}

// ---------------------------------------------------------------------------
// fp32 -> fp16 conversions + field zero
// ---------------------------------------------------------------------------
__global__ void conv_x_kernel(const float* __restrict__ x)
{
    size_t i = (size_t)blockIdx.x * blockDim.x + threadIdx.x;
    float4 v = reinterpret_cast<const float4*>(x)[i];
    __half2* X = reinterpret_cast<__half2*>(g_x);
    X[2*i]   = __half2(__float2half(v.x), __float2half(v.y));
    X[2*i+1] = __half2(__float2half(v.z), __float2half(v.w));
}

__global__ void conv_wkv_kernel(const float* __restrict__ kw, const float* __restrict__ vw)
{
    size_t i = (size_t)blockIdx.x * blockDim.x + threadIdx.x;   // over 2048*1024/4
    size_t e = i * 4;
    int r = (int)(e >> 10), c = (int)(e & 1023);
    int h = r >> 7, r7 = r & 127;
    const float* src = (r7 < 64) ? (kw + ((size_t)(h*64 + r7)) * DD + c)
                                 : (vw + ((size_t)(h*64 + r7 - 64)) * DD + c);
    float4 v = *reinterpret_cast<const float4*>(src);
    __half2* W = reinterpret_cast<__half2*>(g_wkv);
    W[2*i]   = __half2(__float2half(v.x), __float2half(v.y));
    W[2*i+1] = __half2(__float2half(v.z), __float2half(v.w));
}

__global__ void conv_ow_kernel(const float* __restrict__ ow)
{
    size_t i = (size_t)blockIdx.x * blockDim.x + threadIdx.x;
    float4 v = reinterpret_cast<const float4*>(ow)[i];
    __half2* W = reinterpret_cast<__half2*>(g_ow);
    W[2*i]   = __half2(__float2half(v.x), __float2half(v.y));
    W[2*i+1] = __half2(__float2half(v.z), __float2half(v.w));
}

__global__ void zero_field_kernel()
{
    size_t i = (size_t)blockIdx.x * blockDim.x + threadIdx.x;   // over 2M/4
    reinterpret_cast<float4*>(g_field)[i] = make_float4(0.f, 0.f, 0.f, 0.f);
}

// ---------------------------------------------------------------------------
// shared load (templated on thread count)
// ---------------------------------------------------------------------------
template <int NTHR>
__device__ __forceinline__ void load_stage(
    const __half* __restrict__ gA, const __half* __restrict__ gB,
    int m0, int n0, int kc, uint32_t sbase, int t)
{
    #pragma unroll
    for (int i = 0; i < 1024 / NTHR; ++i) {    // A: 128 rows x 8 chunks of 16B
        int e = t + i * NTHR;
        int row = e >> 3, c = e & 7;
        CP_ASYNC(sbase + swz(row, c),
                 gA + (((size_t)(m0 + row)) << 10) + (size_t)kc * KC + c * 8);
    }
    #pragma unroll
    for (int i = 0; i < 1024 / NTHR; ++i) {    // B
        int e = t + i * NTHR;
        int row = e >> 3, c = e & 7;
        CP_ASYNC(sbase + B_OFF + swz(row, c),
                 gB + (((size_t)(n0 + row)) << 10) + (size_t)kc * KC + c * 8);
    }
}

// ---------------------------------------------------------------------------
// GEMM #1: C[16384,2048] = x @ Wkv^T (fp16), 4 warps, warp tile 64x64,
// 2-stage pipeline, 3 CTAs/SM. Lean epilogue (35KB smem):
//   k-warps: ||k|| in registers (shfl butterfly) -> s_mag
//   v-warps: wv = (v+vb)*mag -> sWV (pitch 68)
//   all: bin-reduce sWV, atomicAdd into g_field
// ---------------------------------------------------------------------------
__global__ __launch_bounds__(128, 3) void kv_gemm_kernel(
    const float* __restrict__ kb, const float* __restrict__ vb)
{
    extern __shared__ char sp[];
    __shared__ float s_kb[64], s_vb[64], s_mag[128];
    const int t    = threadIdx.x;
    const int lane = t & 31;
    const int w    = t >> 5;            // 0..3
    const int m0w  = (w >> 1) * 64;
    const int n0w  = (w & 1) * 64;
    const int m0   = blockIdx.x * 128;  // global token base
    const int h    = blockIdx.y;        // head
    const int n0   = h * 128;
    uint32_t sb = smem_u32(sp);

    if (t < 64)       s_kb[t]      = kb[h * 64 + t];
    else if (t < 128) s_vb[t - 64] = vb[h * 64 + t - 64];

    float acc[4][8][4];
    #pragma unroll
    for (int a = 0; a < 4; ++a)
        #pragma unroll
        for (int b = 0; b < 8; ++b)
            #pragma unroll
            for (int q = 0; q < 4; ++q) acc[a][b][q] = 0.f;

    load_stage<128>(g_x, g_wkv, m0, n0, 0, sb, t); CP_COMMIT();

    for (int s = 0; s < NCH; ++s) {
        if (s + 1 < NCH) {
            load_stage<128>(g_x, g_wkv, m0, n0, s + 1, sb + ((s + 1) & 1) * STAGE, t);
            CP_COMMIT(); CP_WAIT1();
        } else { CP_WAIT0(); }
        __syncthreads();
        uint32_t st = sb + (s & 1) * STAGE;
        #pragma unroll
        for (int kh = 0; kh < 4; ++kh) {
            uint32_t ah[4][4];
            uint32_t arow = (uint32_t)(m0w + (lane & 15));
            uint32_t ac   = (uint32_t)(kh * 2 + (lane >> 4));
            #pragma unroll
            for (int mt = 0; mt < 4; ++mt)
                ldmx4(ah[mt], st + swz(arow + mt * 16, ac));
            uint32_t bh[4][4];
            uint32_t brow = (uint32_t)(n0w + (lane & 7) + ((lane >> 4) << 3));
            uint32_t bc   = (uint32_t)(kh * 2 + ((lane & 8) >> 3));
            #pragma unroll
            for (int bj = 0; bj < 4; ++bj)
                ldmx4(bh[bj], st + B_OFF + swz(brow + bj * 16, bc));
            #pragma unroll
            for (int mt = 0; mt < 4; ++mt)
                #pragma unroll
                for (int nt = 0; nt < 8; ++nt)
                    mma16816(acc[mt][nt], ah[mt], &bh[nt >> 1][(nt & 1) * 2]);
        }
        __syncthreads();
    }

    // ---- epilogue ----
    // k-side warps (n0w==0): per-row ssq via lane partials + butterfly
    if (n0w == 0) {
        #pragma unroll
        for (int mt = 0; mt < 4; ++mt)
            #pragma unroll
            for (int half = 0; half < 2; ++half) {
                float ssq = 0.f;
                #pragma unroll
                for (int nt = 0; nt < 8; ++nt) {
                    int cl = nt * 8 + ((lane & 3) << 1);
                    float k0 = acc[mt][nt][half * 2 + 0] + s_kb[cl];
                    float k1 = acc[mt][nt][half * 2 + 1] + s_kb[cl + 1];
                    ssq = fmaf(k0, k0, fmaf(k1, k1, ssq));
                }
                ssq += __shfl_xor_sync(0xFFFFFFFF, ssq, 1);
                ssq += __shfl_xor_sync(0xFFFFFFFF, ssq, 2);
                if ((lane & 3) == 0)
                    s_mag[m0w + mt * 16 + half * 8 + (lane >> 2)] = sqrtf(ssq);
            }
    }
    __syncthreads();

    // v-side warps (n0w==64): wv into sWV (128 x 64, pitch 68) = 34.8KB
    float* sWV = reinterpret_cast<float*>(sp);
    if (n0w == 64) {
        #pragma unroll
        for (int mt = 0; mt < 4; ++mt)
            #pragma unroll
            for (int half = 0; half < 2; ++half) {
                int r = m0w + mt * 16 + half * 8 + (lane >> 2);
                float m = s_mag[r];
                #pragma unroll
                for (int nt = 0; nt < 8; ++nt) {
                    int cl = nt * 8 + ((lane & 3) << 1);
                    sWV[r * 68 + cl]     = (acc[mt][nt][half * 2 + 0] + s_vb[cl])     * m;
                    sWV[r * 68 + cl + 1] = (acc[mt][nt][half * 2 + 1] + s_vb[cl + 1]) * m;
                }
            }
    }
    __syncthreads();

    // bin reduction: one atomicAdd per (bin, d)
    {
        const int b      = m0 >> 12;            // batch (4096 tokens each)
        const int nloc0  = m0 & (NN - 1);       // token base within batch
        const int g_lo   = bin_of(nloc0);
        const int g_hi   = bin_of(nloc0 + 127);
        const int nb     = g_hi - g_lo + 1;     // <= 18
        float* fdst = g_field + (((size_t)(b * HH + h)) * GG << 6);
        for (int idx = t; idx < nb * 64; idx += 128) {
            int bin = g_lo + (idx >> 6);
            int d   = idx & 63;
            int n   = (int)(((long long)bin * 4095) / 511) - 2;
            if (n < 0) n = 0;
            while (bin_of(n) < bin) ++n;
            if (n < nloc0) n = nloc0;
            float s = 0.f;
            for (; n < nloc0 + 128 && n < NN && bin_of(n) == bin; ++n)
                s += sWV[(n - nloc0) * 68 + d];
            atomicAdd(fdst + ((size_t)bin << 6) + d, s);
        }
    }
}

// ---------------------------------------------------------------------------
// GEMM #2: out rows = A @ ow^T + ob, scattered directly to all tokens per bin
// ---------------------------------------------------------------------------
__global__ __launch_bounds__(256, 2) void out_gemm_kernel(
    const float* __restrict__ ob, float* __restrict__ out)
{
    extern __shared__ char sp[];
    __shared__ float s_ob[128];
    const int t    = threadIdx.x;
    const int lane = t & 31;
    const int w    = t >> 5;
    const int m0w  = (w >> 2) * 64;
    const int n0w  = (w & 3) * 32;
    const int m0   = blockIdx.x * 128;    // rows m = b*512 + g
    const int j0   = blockIdx.y * 128;
    uint32_t sb = smem_u32(sp);

    if (t < 128) s_ob[t] = ob[j0 + t];

    float acc[4][4][4];
    #pragma unroll
    for (int a = 0; a < 4; ++a)
        #pragma unroll
        for (int b = 0; b < 4; ++b)
            #pragma unroll
            for (int q = 0; q < 4; ++q) acc[a][b][q] = 0.f;

    load_stage<256>(g_A, g_ow, m0, j0, 0, sb,         t); CP_COMMIT();
    load_stage<256>(g_A, g_ow, m0, j0, 1, sb + STAGE, t); CP_COMMIT();

    for (int s = 0; s < NCH; ++s) {
        if (s + 2 < NCH) { CP_WAIT1(); } else { CP_WAIT0(); }
        __syncthreads();
        if (s + 2 < NCH) {
            load_stage<256>(g_A, g_ow, m0, j0, s + 2, sb + ((s + 2) % 3) * STAGE, t);
            CP_COMMIT();
        }
        uint32_t st = sb + (s % 3) * STAGE;
        #pragma unroll
        for (int kh = 0; kh < 4; ++kh) {
            uint32_t ah[4][4];
            uint32_t arow = (uint32_t)(m0w + (lane & 15));
            uint32_t ac   = (uint32_t)(kh * 2 + (lane >> 4));
            #pragma unroll
            for (int mt = 0; mt < 4; ++mt)
                ldmx4(ah[mt], st + swz(arow + mt * 16, ac));
            uint32_t bh[2][4];
            uint32_t brow = (uint32_t)(n0w + (lane & 7) + ((lane >> 4) << 3));
            uint32_t bc   = (uint32_t)(kh * 2 + ((lane & 8) >> 3));
            #pragma unroll
            for (int bj = 0; bj < 2; ++bj)
                ldmx4(bh[bj], st + B_OFF + swz(brow + bj * 16, bc));
            #pragma unroll
            for (int mt = 0; mt < 4; ++mt)
                #pragma unroll
                for (int nt = 0; nt < 4; ++nt)
                    mma16816(acc[mt][nt], ah[mt], &bh[nt >> 1][(nt & 1) * 2]);
        }
    }

    // epilogue: scatter each bin-row to every token n with bin_of(n) == g
    const int b = m0 >> 9;          // batch (512 bins per batch)
    #pragma unroll
    for (int mt = 0; mt < 4; ++mt) {
        #pragma unroll
        for (int half = 0; half < 2; ++half) {
            int m = m0 + m0w + mt * 16 + (lane >> 2) + half * 8;
            int g = m & 511;
            int n = (int)(((long long)g * 4095) / 511) - 2;
            if (n < 0) n = 0;
            while (bin_of(n) < g) ++n;
            for (; n < NN && bin_of(n) == g; ++n) {
                float* dst = out + (((size_t)(b * NN + n)) << 10) + j0;
                #pragma unroll
                for (int nt = 0; nt < 4; ++nt) {
                    int cl = n0w + nt * 8 + ((lane & 3) << 1);
                    float2 o;
                    o.x = acc[mt][nt][half * 2 + 0] + s_ob[cl];
                    o.y = acc[mt][nt][half * 2 + 1] + s_ob[cl + 1];
                    *reinterpret_cast<float2*>(dst + cl) = o;
                }
            }
        }
    }
}

// ---------------------------------------------------------------------------
// circular exp-kernel convolution (anchor + geometric recursion);
// writes the out-GEMM A matrix directly: fp16, layout (b*512+g, h*64+d)
// ---------------------------------------------------------------------------
#define TAPS 144
__global__ void conv_kernel()
{
    extern __shared__ float sf[];
    __shared__ float wsh[TAPS];
    int bh = blockIdx.x;
    int b  = bh >> 4, h = bh & 15;
    const float* F = g_field + (size_t)bh * GG * HDIM;
    for (int i = threadIdx.x; i < GG * HDIM; i += blockDim.x)
        sf[i] = F[i];
    if (threadIdx.x < TAPS) {
        float Z = 0.f;
        for (int dd = 256; dd >= 1; --dd) Z += expf(-(float)dd / 3.0f);
        Z += 1e-8f;
        wsh[threadIdx.x] = expf(-(float)(threadIdx.x + 1) / 3.0f) / Z;
    }
    __syncthreads();

    int d    = threadIdx.x & 63;
    int g0   = (threadIdx.x >> 6) * 64;
    int gtop = g0 + 63;

    float acc = 0.f;
    for (int j = TAPS - 1; j >= 0; --j)
        acc = fmaf(wsh[j], sf[((gtop + 257 + j) & 511) * HDIM + d], acc);

    __half* outA = g_A + ((size_t)b * GG << 10) + h * 64 + d;
    outA[(size_t)gtop << 10] = __float2half(acc);

    const float a  = 0.7165313105737893f;
    const float w0 = wsh[0];
    float C = acc;
    for (int g = gtop - 1; g >= g0; --g) {
        C = fmaf(a, C, w0 * sf[((g + 257) & 511) * HDIM + d]);
        outA[(size_t)g << 10] = __float2half(C);
    }
}

// ---------------------------------------------------------------------------
extern "C" void kernel_launch(void* const* d_in, const int* in_sizes, int n_in,
                              void* d_out, int out_size)
{
    const float* x  = (const float*)d_in[0];
    // d_in[1], d_in[2] are q_w, q_b — unused by the reference output.
    const float* kw = (const float*)d_in[3];
    const float* kb = (const float*)d_in[4];
    const float* vw = (const float*)d_in[5];
    const float* vb = (const float*)d_in[6];
    const float* ow = (const float*)d_in[7];
    const float* ob = (const float*)d_in[8];
    float* out = (float*)d_out;

    cudaFuncSetAttribute(kv_gemm_kernel,  cudaFuncAttributeMaxDynamicSharedMemorySize, KV_SMEM);
    cudaFuncSetAttribute(out_gemm_kernel, cudaFuncAttributeMaxDynamicSharedMemorySize, OUT_SMEM);
    cudaFuncSetAttribute(conv_kernel, cudaFuncAttributeMaxDynamicSharedMemorySize,
                         GG * HDIM * (int)sizeof(float));

    conv_x_kernel<<<(BNTOK * DD / 4) / 256, 256>>>(x);
    conv_wkv_kernel<<<(2048 * DD / 4) / 256, 256>>>(kw, vw);
    conv_ow_kernel<<<(DD * DD / 4) / 256, 256>>>(ow);
    zero_field_kernel<<<(BB * HH * GG * HDIM / 4) / 256, 256>>>();

    kv_gemm_kernel<<<dim3(BNTOK / 128, HH), 128, KV_SMEM>>>(kb, vb);

    conv_kernel<<<BB * HH, 512, GG * HDIM * sizeof(float)>>>();

    out_gemm_kernel<<<dim3((BB * GG) / 128, DD / 128), 256, OUT_SMEM>>>(ob, out);
}

// round 11
// speedup vs baseline: 1.1012x; 1.1012x over previous
#include <cuda_runtime.h>
#include <cuda_fp16.h>
#include <math.h>
#include <stdint.h>

#define BB 4
#define NN 4096
#define DD 1024
#define HH 16
#define HDIM 64
#define GG 512
#define BNTOK (BB*NN)

// ---------------- scratch (device globals; no allocations allowed) ----------
__device__ float  g_field[(size_t)BB * HH * GG * HDIM]; // 8MB (fully written, no atomics)
__device__ float  g_mag [(size_t)BNTOK * HH];           // 1MB  ||k|| per (token, head)
__device__ float  g_S   [(size_t)BB * GG * HH];         // 128KB sum of mags per (bin, head)
__device__ __half g_x   [(size_t)BNTOK * DD];           // 32MB fp16 x
__device__ __half g_kw  [(size_t)DD * DD];              // 2MB
__device__ __half g_vw  [(size_t)DD * DD];              // 2MB
__device__ __half g_ow  [(size_t)DD * DD];              // 2MB
__device__ __half g_Y   [(size_t)BB * GG * HH * DD];    // 64MB weighted segsum of x
__device__ __half g_A   [(size_t)BB * GG * DD];         // 4MB  conv result, repacked

// Replicates jnp: pos = (n/4095.0f)*511.0f ; int32 trunc ; clip
__device__ __forceinline__ int bin_of(int n) {
    float p = ((float)n / 4095.0f) * 511.0f;
    int g = (int)p;
    g = g < 0 ? 0 : g;
    return g > 511 ? 511 : g;
}

// ---------------- baseline-PTX tensor helpers (sm_80+, ok on compute_103) ---
__device__ __forceinline__ uint32_t smem_u32(const void* p) {
    uint32_t a;
    asm("{ .reg .u64 t; cvta.to.shared.u64 t, %1; cvt.u32.u64 %0, t; }" : "=r"(a) : "l"(p));
    return a;
}
__device__ __forceinline__ void ldmx4(uint32_t* r, uint32_t a) {
    asm volatile("ldmatrix.sync.aligned.m8n8.x4.shared.b16 {%0,%1,%2,%3}, [%4];"
        : "=r"(r[0]), "=r"(r[1]), "=r"(r[2]), "=r"(r[3]) : "r"(a));
}
__device__ __forceinline__ void mma16816(float* c, const uint32_t* a, const uint32_t* b) {
    asm volatile("mma.sync.aligned.m16n8k16.row.col.f32.f16.f16.f32 "
        "{%0,%1,%2,%3}, {%4,%5,%6,%7}, {%8,%9}, {%0,%1,%2,%3};"
        : "+f"(c[0]), "+f"(c[1]), "+f"(c[2]), "+f"(c[3])
        : "r"(a[0]), "r"(a[1]), "r"(a[2]), "r"(a[3]), "r"(b[0]), "r"(b[1]));
}
#define CP_ASYNC(d, s) asm volatile("cp.async.cg.shared.global [%0], [%1], 16;" :: "r"(d), "l"(s) : "memory")
#define CP_COMMIT()    asm volatile("cp.async.commit_group;" ::: "memory")
#define CP_WAIT1()     asm volatile("cp.async.wait_group 1;" ::: "memory")
#define CP_WAIT0()     asm volatile("cp.async.wait_group 0;" ::: "memory")

#define KC    64
#define NCH   16                  // 1024 / 64
#define B_OFF 16384               // A tile is always 128 rows x 128B

// swizzled byte offset for (row, 16B-chunk c in 0..7)
__device__ __forceinline__ uint32_t swz(uint32_t row, uint32_t c) {
    return row * 128u + ((c ^ (row & 7u)) << 4);
}

// generic tile loader: gA/gB pre-offset to (row0, kc*KC)
template <int NTHR, int AROWS, int BROWS>
__device__ __forceinline__ void load_tiles(
    const __half* __restrict__ gA, size_t strideA,
    const __half* __restrict__ gB, size_t strideB,
    uint32_t sbase, int t)
{
    #pragma unroll
    for (int i = 0; i < AROWS * 8 / NTHR; ++i) {
        int e = t + i * NTHR;
        int row = e >> 3, c = e & 7;
        CP_ASYNC(sbase + swz(row, c), gA + (size_t)row * strideA + c * 8);
    }
    #pragma unroll
    for (int i = 0; i < BROWS * 8 / NTHR; ++i) {
        int e = t + i * NTHR;
        int row = e >> 3, c = e & 7;
        CP_ASYNC(sbase + B_OFF + swz(row, c), gB + (size_t)row * strideB + c * 8);
    }
}

// 64x32 warp-tile compute over one KC=64 stage
__device__ __forceinline__ void compute64x32(uint32_t st, int m0w, int n0w, int lane,
                                             float acc[4][4][4])
{
    #pragma unroll
    for (int kh = 0; kh < 4; ++kh) {
        uint32_t ah[4][4];
        uint32_t arow = (uint32_t)(m0w + (lane & 15));
        uint32_t ac   = (uint32_t)(kh * 2 + (lane >> 4));
        #pragma unroll
        for (int mt = 0; mt < 4; ++mt)
            ldmx4(ah[mt], st + swz(arow + mt * 16, ac));
        uint32_t bh[2][4];
        uint32_t brow = (uint32_t)(n0w + (lane & 7) + ((lane >> 4) << 3));
        uint32_t bc   = (uint32_t)(kh * 2 + ((lane & 8) >> 3));
        #pragma unroll
        for (int bj = 0; bj < 2; ++bj)
            ldmx4(bh[bj], st + B_OFF + swz(brow + bj * 16, bc));
        #pragma unroll
        for (int mt = 0; mt < 4; ++mt)
            #pragma unroll
            for (int nt = 0; nt < 4; ++nt)
                mma16816(acc[mt][nt], ah[mt], &bh[nt >> 1][(nt & 1) * 2]);
    }
}

// ---------------------------------------------------------------------------
// prep: all fp32->fp16 conversions merged in one launch
// blocks: [0,16384) x | [16384,17408) kw | [17408,18432) vw | [18432,19456) ow
// ---------------------------------------------------------------------------
__global__ void prep_kernel(const float* __restrict__ x,  const float* __restrict__ kw,
                            const float* __restrict__ vw, const float* __restrict__ ow)
{
    int bid = blockIdx.x;
    const float* src; __half2* dst; size_t i;
    if (bid < 16384)      { src = x;  dst = (__half2*)g_x;  i = (size_t)bid * 256 + threadIdx.x; }
    else if (bid < 17408) { src = kw; dst = (__half2*)g_kw; i = (size_t)(bid - 16384) * 256 + threadIdx.x; }
    else if (bid < 18432) { src = vw; dst = (__half2*)g_vw; i = (size_t)(bid - 17408) * 256 + threadIdx.x; }
    else                  { src = ow; dst = (__half2*)g_ow; i = (size_t)(bid - 18432) * 256 + threadIdx.x; }
    float4 v = reinterpret_cast<const float4*>(src)[i];
    dst[2*i]   = __half2(__float2half(v.x), __float2half(v.y));
    dst[2*i+1] = __half2(__float2half(v.z), __float2half(v.w));
}

// ---------------------------------------------------------------------------
// GEMM #1 (k only): K = x @ kw^T, fused ||k+kb|| -> g_mag. Block 128 tokens x
// 128 cols (2 heads). 8 warps, warp tile 64x32, 3-stage, 2 CTAs/SM.
// ---------------------------------------------------------------------------
#define KSTAGE 32768
__global__ __launch_bounds__(256, 2) void k_gemm_kernel(const float* __restrict__ kb)
{
    extern __shared__ char sp[];
    __shared__ float s_kb[128];
    __shared__ float s_part[128][4];
    const int t    = threadIdx.x;
    const int lane = t & 31;
    const int w    = t >> 5;
    const int m0w  = (w >> 2) * 64;
    const int n0w  = (w & 3) * 32;
    const int m0   = blockIdx.x * 128;
    const int pair = blockIdx.y;          // head pair: heads 2*pair, 2*pair+1
    const int n0   = pair * 128;
    uint32_t sb = smem_u32(sp);

    if (t < 128) s_kb[t] = kb[pair * 128 + t];

    float acc[4][4][4];
    #pragma unroll
    for (int a = 0; a < 4; ++a)
        #pragma unroll
        for (int b = 0; b < 4; ++b)
            #pragma unroll
            for (int q = 0; q < 4; ++q) acc[a][b][q] = 0.f;

    const __half* Abase = g_x  + (size_t)m0 * DD;
    const __half* Bbase = g_kw + (size_t)n0 * DD;

    load_tiles<256,128,128>(Abase,          DD, Bbase,          DD, sb,          t); CP_COMMIT();
    load_tiles<256,128,128>(Abase + KC,     DD, Bbase + KC,     DD, sb + KSTAGE, t); CP_COMMIT();

    for (int s = 0; s < NCH; ++s) {
        if (s + 2 < NCH) { CP_WAIT1(); } else { CP_WAIT0(); }
        __syncthreads();
        if (s + 2 < NCH) {
            load_tiles<256,128,128>(Abase + (s + 2) * KC, DD, Bbase + (s + 2) * KC, DD,
                                    sb + ((s + 2) % 3) * KSTAGE, t);
            CP_COMMIT();
        }
        compute64x32(sb + (s % 3) * KSTAGE, m0w, n0w, lane, acc);
    }

    // epilogue: per-row ssq partial over this warp's 32 cols, butterfly, combine
    #pragma unroll
    for (int mt = 0; mt < 4; ++mt)
        #pragma unroll
        for (int half = 0; half < 2; ++half) {
            float ssq = 0.f;
            #pragma unroll
            for (int nt = 0; nt < 4; ++nt) {
                int cl = n0w + nt * 8 + ((lane & 3) << 1);
                float k0 = acc[mt][nt][half * 2 + 0] + s_kb[cl];
                float k1 = acc[mt][nt][half * 2 + 1] + s_kb[cl + 1];
                ssq = fmaf(k0, k0, fmaf(k1, k1, ssq));
            }
            ssq += __shfl_xor_sync(0xFFFFFFFF, ssq, 1);
            ssq += __shfl_xor_sync(0xFFFFFFFF, ssq, 2);
            if ((lane & 3) == 0)
                s_part[m0w + mt * 16 + half * 8 + (lane >> 2)][w & 3] = ssq;
        }
    __syncthreads();

    if (t < 128) {
        int tok = m0 + t;
        g_mag[(size_t)tok * HH + pair * 2]     = sqrtf(s_part[t][0] + s_part[t][1]);
        g_mag[(size_t)tok * HH + pair * 2 + 1] = sqrtf(s_part[t][2] + s_part[t][3]);
    }
}

// ---------------------------------------------------------------------------
// ysum: Y[bin,h,:] = sum_{n in bin} mag[n,h] * x[n,:]; S[bin,h] = sum mag
// One block per bin (b*512+g), 256 threads.
// ---------------------------------------------------------------------------
__global__ void ysum_kernel()
{
    __shared__ float sm[9 * 16];
    const int m = blockIdx.x;            // b*512 + g
    const int b = m >> 9, g = m & 511;
    const int t = threadIdx.x;

    int n = (int)(((long long)g * 4095) / 511) - 2;
    if (n < 0) n = 0;
    while (bin_of(n) < g) ++n;
    const int ns = n;
    int ne = n;
    while (ne < NN && bin_of(ne) == g) ++ne;
    const int cnt = ne - ns;             // 1..9

    if (t < cnt * 16)
        sm[t] = g_mag[((size_t)(b * NN + ns + (t >> 4))) * HH + (t & 15)];
    __syncthreads();

    #pragma unroll
    for (int jj = 0; jj < 4; ++jj) {
        int c = t + jj * 256;
        float xv[9];
        for (int i = 0; i < cnt; ++i)
            xv[i] = __half2float(g_x[((size_t)(b * NN + ns + i)) * DD + c]);
        for (int h = 0; h < 16; ++h) {
            float s = 0.f;
            for (int i = 0; i < cnt; ++i)
                s = fmaf(sm[i * 16 + h], xv[i], s);
            g_Y[((size_t)m * HH + h) * DD + c] = __float2half(s);
        }
    }
    if (t < 16) {
        float s = 0.f;
        for (int i = 0; i < cnt; ++i) s += sm[i * 16 + t];
        g_S[(size_t)m * HH + t] = s;
    }
}

// ---------------------------------------------------------------------------
// GEMM #2: field[bin,h,:] = Y[bin,h,:] @ vw_h^T + S*vb_h
// Block 128 bins x 64 cols, 4 warps (64x32 tiles), 3-stage, 3 CTAs/SM.
// ---------------------------------------------------------------------------
#define FSTAGE 24576
__global__ __launch_bounds__(128, 3) void f_gemm_kernel(const float* __restrict__ vb)
{
    extern __shared__ char sp[];
    __shared__ float s_vb[64], s_S[128];
    const int t    = threadIdx.x;
    const int lane = t & 31;
    const int w    = t >> 5;
    const int m0w  = (w >> 1) * 64;
    const int n0w  = (w & 1) * 32;
    const int m0   = blockIdx.x * 128;    // bins (b*512+g)
    const int h    = blockIdx.y;
    uint32_t sb = smem_u32(sp);

    if (t < 64) s_vb[t] = vb[h * 64 + t];
    s_S[t] = g_S[(size_t)(m0 + t) * HH + h];
    if (t + 128 < 128) {}                 // (blockDim==128 covers s_S fully? no)
    // blockDim = 128 threads cover s_S[128] exactly. ok.

    float acc[4][4][4];
    #pragma unroll
    for (int a = 0; a < 4; ++a)
        #pragma unroll
        for (int b = 0; b < 4; ++b)
            #pragma unroll
            for (int q = 0; q < 4; ++q) acc[a][b][q] = 0.f;

    const __half* Abase = g_Y  + ((size_t)m0 * HH + h) * DD;
    const __half* Bbase = g_vw + (size_t)(h * 64) * DD;
    const size_t strA = (size_t)HH * DD;  // 16384

    load_tiles<128,128,64>(Abase,      strA, Bbase,      DD, sb,          t); CP_COMMIT();
    load_tiles<128,128,64>(Abase + KC, strA, Bbase + KC, DD, sb + FSTAGE, t); CP_COMMIT();

    for (int s = 0; s < NCH; ++s) {
        if (s + 2 < NCH) { CP_WAIT1(); } else { CP_WAIT0(); }
        __syncthreads();
        if (s + 2 < NCH) {
            load_tiles<128,128,64>(Abase + (s + 2) * KC, strA, Bbase + (s + 2) * KC, DD,
                                   sb + ((s + 2) % 3) * FSTAGE, t);
            CP_COMMIT();
        }
        compute64x32(sb + (s % 3) * FSTAGE, m0w, n0w, lane, acc);
    }

    // epilogue: field[(b*16+h)*512+g][d] = acc + S*vb
    #pragma unroll
    for (int mt = 0; mt < 4; ++mt)
        #pragma unroll
        for (int half = 0; half < 2; ++half) {
            int mloc = m0w + mt * 16 + half * 8 + (lane >> 2);
            int m = m0 + mloc;
            int b = m >> 9, g = m & 511;
            float Sv = s_S[mloc];
            float* dst = g_field + ((((size_t)(b * HH + h)) * GG + g) << 6);
            #pragma unroll
            for (int nt = 0; nt < 4; ++nt) {
                int cl = n0w + nt * 8 + ((lane & 3) << 1);
                float2 o;
                o.x = acc[mt][nt][half * 2 + 0] + Sv * s_vb[cl];
                o.y = acc[mt][nt][half * 2 + 1] + Sv * s_vb[cl + 1];
                *reinterpret_cast<float2*>(dst + cl) = o;
            }
        }
}

// ---------------------------------------------------------------------------
// circular exp-kernel convolution (anchor + geometric recursion);
// writes the out-GEMM A matrix directly: fp16, layout (b*512+g, h*64+d)
// ---------------------------------------------------------------------------
#define TAPS 144
__global__ void conv_kernel()
{
    extern __shared__ float sf[];
    __shared__ float wsh[TAPS];
    int bh = blockIdx.x;
    int b  = bh >> 4, h = bh & 15;
    const float* F = g_field + (size_t)bh * GG * HDIM;
    for (int i = threadIdx.x; i < GG * HDIM; i += blockDim.x)
        sf[i] = F[i];
    if (threadIdx.x < TAPS) {
        float Z = 0.f;
        for (int dd = 256; dd >= 1; --dd) Z += expf(-(float)dd / 3.0f);
        Z += 1e-8f;
        wsh[threadIdx.x] = expf(-(float)(threadIdx.x + 1) / 3.0f) / Z;
    }
    __syncthreads();

    int d    = threadIdx.x & 63;
    int g0   = (threadIdx.x >> 6) * 64;
    int gtop = g0 + 63;

    float acc = 0.f;
    for (int j = TAPS - 1; j >= 0; --j)
        acc = fmaf(wsh[j], sf[((gtop + 257 + j) & 511) * HDIM + d], acc);

    __half* outA = g_A + ((size_t)b * GG << 10) + h * 64 + d;
    outA[(size_t)gtop << 10] = __float2half(acc);

    const float a  = 0.7165313105737893f;
    const float w0 = wsh[0];
    float C = acc;
    for (int g = gtop - 1; g >= g0; --g) {
        C = fmaf(a, C, w0 * sf[((g + 257) & 511) * HDIM + d]);
        outA[(size_t)g << 10] = __float2half(C);
    }
}

// ---------------------------------------------------------------------------
// GEMM #3: out rows = A @ ow^T + ob, scattered to all tokens per bin.
// Block 128 bins x 64 cols, 4 warps, 3-stage, 3 CTAs/SM; grid (16,16).
// ---------------------------------------------------------------------------
__global__ __launch_bounds__(128, 3) void out_gemm_kernel(
    const float* __restrict__ ob, float* __restrict__ out)
{
    extern __shared__ char sp[];
    __shared__ float s_ob[64];
    const int t    = threadIdx.x;
    const int lane = t & 31;
    const int w    = t >> 5;
    const int m0w  = (w >> 1) * 64;
    const int n0w  = (w & 1) * 32;
    const int m0   = blockIdx.x * 128;    // rows m = b*512 + g
    const int j0   = blockIdx.y * 64;
    uint32_t sb = smem_u32(sp);

    if (t < 64) s_ob[t] = ob[j0 + t];

    float acc[4][4][4];
    #pragma unroll
    for (int a = 0; a < 4; ++a)
        #pragma unroll
        for (int b = 0; b < 4; ++b)
            #pragma unroll
            for (int q = 0; q < 4; ++q) acc[a][b][q] = 0.f;

    const __half* Abase = g_A  + (size_t)m0 * DD;
    const __half* Bbase = g_ow + (size_t)j0 * DD;

    load_tiles<128,128,64>(Abase,      DD, Bbase,      DD, sb,          t); CP_COMMIT();
    load_tiles<128,128,64>(Abase + KC, DD, Bbase + KC, DD, sb + FSTAGE, t); CP_COMMIT();

    for (int s = 0; s < NCH; ++s) {
        if (s + 2 < NCH) { CP_WAIT1(); } else { CP_WAIT0(); }
        __syncthreads();
        if (s + 2 < NCH) {
            load_tiles<128,128,64>(Abase + (s + 2) * KC, DD, Bbase + (s + 2) * KC, DD,
                                   sb + ((s + 2) % 3) * FSTAGE, t);
            CP_COMMIT();
        }
        compute64x32(sb + (s % 3) * FSTAGE, m0w, n0w, lane, acc);
    }

    // epilogue: scatter each bin-row to every token n with bin_of(n) == g
    const int b = m0 >> 9;
    #pragma unroll
    for (int mt = 0; mt < 4; ++mt) {
        #pragma unroll
        for (int half = 0; half < 2; ++half) {
            int m = m0 + m0w + mt * 16 + (lane >> 2) + half * 8;
            int g = m & 511;
            int n = (int)(((long long)g * 4095) / 511) - 2;
            if (n < 0) n = 0;
            while (bin_of(n) < g) ++n;
            for (; n < NN && bin_of(n) == g; ++n) {
                float* dst = out + (((size_t)(b * NN + n)) << 10) + j0;
                #pragma unroll
                for (int nt = 0; nt < 4; ++nt) {
                    int cl = n0w + nt * 8 + ((lane & 3) << 1);
                    float2 o;
                    o.x = acc[mt][nt][half * 2 + 0] + s_ob[cl];
                    o.y = acc[mt][nt][half * 2 + 1] + s_ob[cl + 1];
                    *reinterpret_cast<float2*>(dst + cl) = o;
                }
            }
        }
    }
}

// ---------------------------------------------------------------------------
extern "C" void kernel_launch(void* const* d_in, const int* in_sizes, int n_in,
                              void* d_out, int out_size)
{
    const float* x  = (const float*)d_in[0];
    // d_in[1], d_in[2] are q_w, q_b — unused by the reference output.
    const float* kw = (const float*)d_in[3];
    const float* kb = (const float*)d_in[4];
    const float* vw = (const float*)d_in[5];
    const float* vb = (const float*)d_in[6];
    const float* ow = (const float*)d_in[7];
    const float* ob = (const float*)d_in[8];
    float* out = (float*)d_out;

    cudaFuncSetAttribute(k_gemm_kernel,   cudaFuncAttributeMaxDynamicSharedMemorySize, 3 * KSTAGE);
    cudaFuncSetAttribute(f_gemm_kernel,   cudaFuncAttributeMaxDynamicSharedMemorySize, 3 * FSTAGE);
    cudaFuncSetAttribute(out_gemm_kernel, cudaFuncAttributeMaxDynamicSharedMemorySize, 3 * FSTAGE);
    cudaFuncSetAttribute(conv_kernel, cudaFuncAttributeMaxDynamicSharedMemorySize,
                         GG * HDIM * (int)sizeof(float));

    prep_kernel<<<19456, 256>>>(x, kw, vw, ow);

    k_gemm_kernel<<<dim3(BNTOK / 128, 8), 256, 3 * KSTAGE>>>(kb);

    ysum_kernel<<<BB * GG, 256>>>();

    f_gemm_kernel<<<dim3((BB * GG) / 128, HH), 128, 3 * FSTAGE>>>(vb);

    conv_kernel<<<BB * HH, 512, GG * HDIM * sizeof(float)>>>();

    out_gemm_kernel<<<dim3((BB * GG) / 128, DD / 64), 128, 3 * FSTAGE>>>(ob, out);
}

// round 12
// speedup vs baseline: 1.2062x; 1.0953x over previous
#include <cuda_runtime.h>
#include <cuda_fp16.h>
#include <math.h>
#include <stdint.h>

#define BB 4
#define NN 4096
#define DD 1024
#define HH 16
#define HDIM 64
#define GG 512
#define BNTOK (BB*NN)

// ---------------- scratch (device globals; no allocations allowed) ----------
__device__ float  g_field[(size_t)BB * HH * GG * HDIM]; // 8MB
__device__ float  g_mag [(size_t)BNTOK * HH];           // 1MB  ||k|| per (token, head)
__device__ float  g_S   [(size_t)BB * GG * HH];         // 128KB sum of mags per (bin, head)
__device__ __half g_x   [(size_t)BNTOK * DD];           // 32MB fp16 x
__device__ __half g_kw  [(size_t)DD * DD];              // 2MB
__device__ __half g_vw  [(size_t)DD * DD];              // 2MB
__device__ __half g_ow  [(size_t)DD * DD];              // 2MB
__device__ __half g_Y   [(size_t)BB * GG * HH * DD];    // 64MB weighted segsum of x
__device__ __half g_A   [(size_t)BB * GG * DD];         // 4MB  conv result, repacked

// Replicates jnp: pos = (n/4095.0f)*511.0f ; int32 trunc ; clip
__device__ __forceinline__ int bin_of(int n) {
    float p = ((float)n / 4095.0f) * 511.0f;
    int g = (int)p;
    g = g < 0 ? 0 : g;
    return g > 511 ? 511 : g;
}

// ---------------- baseline-PTX tensor helpers (sm_80+, ok on compute_103) ---
__device__ __forceinline__ uint32_t smem_u32(const void* p) {
    uint32_t a;
    asm("{ .reg .u64 t; cvta.to.shared.u64 t, %1; cvt.u32.u64 %0, t; }" : "=r"(a) : "l"(p));
    return a;
}
__device__ __forceinline__ void ldmx4(uint32_t* r, uint32_t a) {
    asm volatile("ldmatrix.sync.aligned.m8n8.x4.shared.b16 {%0,%1,%2,%3}, [%4];"
        : "=r"(r[0]), "=r"(r[1]), "=r"(r[2]), "=r"(r[3]) : "r"(a));
}
__device__ __forceinline__ void mma16816(float* c, const uint32_t* a, const uint32_t* b) {
    asm volatile("mma.sync.aligned.m16n8k16.row.col.f32.f16.f16.f32 "
        "{%0,%1,%2,%3}, {%4,%5,%6,%7}, {%8,%9}, {%0,%1,%2,%3};"
        : "+f"(c[0]), "+f"(c[1]), "+f"(c[2]), "+f"(c[3])
        : "r"(a[0]), "r"(a[1]), "r"(a[2]), "r"(a[3]), "r"(b[0]), "r"(b[1]));
}
#define CP_ASYNC(d, s) asm volatile("cp.async.cg.shared.global [%0], [%1], 16;" :: "r"(d), "l"(s) : "memory")
#define CP_COMMIT()    asm volatile("cp.async.commit_group;" ::: "memory")
#define CP_WAIT1()     asm volatile("cp.async.wait_group 1;" ::: "memory")
#define CP_WAIT0()     asm volatile("cp.async.wait_group 0;" ::: "memory")

#define KC    64
#define NCH   16                  // 1024 / 64

// swizzled byte offset for (row, 16B-chunk c in 0..7)
__device__ __forceinline__ uint32_t swz(uint32_t row, uint32_t c) {
    return row * 128u + ((c ^ (row & 7u)) << 4);
}

// generic tile loader: gA/gB pre-offset to (row0, kc*KC). BOFF = AROWS*128.
template <int NTHR, int AROWS, int BROWS, int BOFF>
__device__ __forceinline__ void load_tiles(
    const __half* __restrict__ gA, size_t strideA,
    const __half* __restrict__ gB, size_t strideB,
    uint32_t sbase, int t)
{
    #pragma unroll
    for (int i = 0; i < AROWS * 8 / NTHR; ++i) {
        int e = t + i * NTHR;
        int row = e >> 3, c = e & 7;
        CP_ASYNC(sbase + swz(row, c), gA + (size_t)row * strideA + c * 8);
    }
    #pragma unroll
    for (int i = 0; i < BROWS * 8 / NTHR; ++i) {
        int e = t + i * NTHR;
        int row = e >> 3, c = e & 7;
        CP_ASYNC(sbase + BOFF + swz(row, c), gB + (size_t)row * strideB + c * 8);
    }
}

// 64x32 warp-tile compute over one KC=64 stage (A tile 128 rows; BOFF 16384)
__device__ __forceinline__ void compute64x32(uint32_t st, int m0w, int n0w, int lane,
                                             float acc[4][4][4])
{
    #pragma unroll
    for (int kh = 0; kh < 4; ++kh) {
        uint32_t ah[4][4];
        uint32_t arow = (uint32_t)(m0w + (lane & 15));
        uint32_t ac   = (uint32_t)(kh * 2 + (lane >> 4));
        #pragma unroll
        for (int mt = 0; mt < 4; ++mt)
            ldmx4(ah[mt], st + swz(arow + mt * 16, ac));
        uint32_t bh[2][4];
        uint32_t brow = (uint32_t)(n0w + (lane & 7) + ((lane >> 4) << 3));
        uint32_t bc   = (uint32_t)(kh * 2 + ((lane & 8) >> 3));
        #pragma unroll
        for (int bj = 0; bj < 2; ++bj)
            ldmx4(bh[bj], st + 16384 + swz(brow + bj * 16, bc));
        #pragma unroll
        for (int mt = 0; mt < 4; ++mt)
            #pragma unroll
            for (int nt = 0; nt < 4; ++nt)
                mma16816(acc[mt][nt], ah[mt], &bh[nt >> 1][(nt & 1) * 2]);
    }
}

// 32x32 warp-tile compute over one KC=64 stage (A tile 64 rows; BOFF 8192)
__device__ __forceinline__ void compute32x32(uint32_t st, int m0w, int n0w, int lane,
                                             float acc[2][4][4])
{
    #pragma unroll
    for (int kh = 0; kh < 4; ++kh) {
        uint32_t ah[2][4];
        uint32_t arow = (uint32_t)(m0w + (lane & 15));
        uint32_t ac   = (uint32_t)(kh * 2 + (lane >> 4));
        #pragma unroll
        for (int mt = 0; mt < 2; ++mt)
            ldmx4(ah[mt], st + swz(arow + mt * 16, ac));
        uint32_t bh[2][4];
        uint32_t brow = (uint32_t)(n0w + (lane & 7) + ((lane >> 4) << 3));
        uint32_t bc   = (uint32_t)(kh * 2 + ((lane & 8) >> 3));
        #pragma unroll
        for (int bj = 0; bj < 2; ++bj)
            ldmx4(bh[bj], st + 8192 + swz(brow + bj * 16, bc));
        #pragma unroll
        for (int mt = 0; mt < 2; ++mt)
            #pragma unroll
            for (int nt = 0; nt < 4; ++nt)
                mma16816(acc[mt][nt], ah[mt], &bh[nt >> 1][(nt & 1) * 2]);
    }
}

// ---------------------------------------------------------------------------
// prep: all fp32->fp16 conversions merged in one launch
// ---------------------------------------------------------------------------
__global__ void prep_kernel(const float* __restrict__ x,  const float* __restrict__ kw,
                            const float* __restrict__ vw, const float* __restrict__ ow)
{
    int bid = blockIdx.x;
    const float* src; __half2* dst; size_t i;
    if (bid < 16384)      { src = x;  dst = (__half2*)g_x;  i = (size_t)bid * 256 + threadIdx.x; }
    else if (bid < 17408) { src = kw; dst = (__half2*)g_kw; i = (size_t)(bid - 16384) * 256 + threadIdx.x; }
    else if (bid < 18432) { src = vw; dst = (__half2*)g_vw; i = (size_t)(bid - 17408) * 256 + threadIdx.x; }
    else                  { src = ow; dst = (__half2*)g_ow; i = (size_t)(bid - 18432) * 256 + threadIdx.x; }
    float4 v = reinterpret_cast<const float4*>(src)[i];
    dst[2*i]   = __half2(__float2half(v.x), __float2half(v.y));
    dst[2*i+1] = __half2(__float2half(v.z), __float2half(v.w));
}

// ---------------------------------------------------------------------------
// GEMM #1 (k only): K = x @ kw^T, fused ||k+kb|| -> g_mag.
// Block 128 tokens x 128 cols (2 heads). 8 warps, 64x32 tiles, 3-stage, 2 CTA/SM.
// ---------------------------------------------------------------------------
#define KSTAGE 32768
__global__ __launch_bounds__(256, 2) void k_gemm_kernel(const float* __restrict__ kb)
{
    extern __shared__ char sp[];
    __shared__ float s_kb[128];
    __shared__ float s_part[128][4];
    const int t    = threadIdx.x;
    const int lane = t & 31;
    const int w    = t >> 5;
    const int m0w  = (w >> 2) * 64;
    const int n0w  = (w & 3) * 32;
    const int m0   = blockIdx.x * 128;
    const int pair = blockIdx.y;          // heads 2*pair, 2*pair+1
    const int n0   = pair * 128;
    uint32_t sb = smem_u32(sp);

    if (t < 128) s_kb[t] = kb[pair * 128 + t];

    float acc[4][4][4];
    #pragma unroll
    for (int a = 0; a < 4; ++a)
        #pragma unroll
        for (int b = 0; b < 4; ++b)
            #pragma unroll
            for (int q = 0; q < 4; ++q) acc[a][b][q] = 0.f;

    const __half* Abase = g_x  + (size_t)m0 * DD;
    const __half* Bbase = g_kw + (size_t)n0 * DD;

    load_tiles<256,128,128,16384>(Abase,      DD, Bbase,      DD, sb,          t); CP_COMMIT();
    load_tiles<256,128,128,16384>(Abase + KC, DD, Bbase + KC, DD, sb + KSTAGE, t); CP_COMMIT();

    for (int s = 0; s < NCH; ++s) {
        if (s + 2 < NCH) { CP_WAIT1(); } else { CP_WAIT0(); }
        __syncthreads();
        if (s + 2 < NCH) {
            load_tiles<256,128,128,16384>(Abase + (s + 2) * KC, DD, Bbase + (s + 2) * KC, DD,
                                          sb + ((s + 2) % 3) * KSTAGE, t);
            CP_COMMIT();
        }
        compute64x32(sb + (s % 3) * KSTAGE, m0w, n0w, lane, acc);
    }

    #pragma unroll
    for (int mt = 0; mt < 4; ++mt)
        #pragma unroll
        for (int half = 0; half < 2; ++half) {
            float ssq = 0.f;
            #pragma unroll
            for (int nt = 0; nt < 4; ++nt) {
                int cl = n0w + nt * 8 + ((lane & 3) << 1);
                float k0 = acc[mt][nt][half * 2 + 0] + s_kb[cl];
                float k1 = acc[mt][nt][half * 2 + 1] + s_kb[cl + 1];
                ssq = fmaf(k0, k0, fmaf(k1, k1, ssq));
            }
            ssq += __shfl_xor_sync(0xFFFFFFFF, ssq, 1);
            ssq += __shfl_xor_sync(0xFFFFFFFF, ssq, 2);
            if ((lane & 3) == 0)
                s_part[m0w + mt * 16 + half * 8 + (lane >> 2)][w & 3] = ssq;
        }
    __syncthreads();

    if (t < 128) {
        int tok = m0 + t;
        g_mag[(size_t)tok * HH + pair * 2]     = sqrtf(s_part[t][0] + s_part[t][1]);
        g_mag[(size_t)tok * HH + pair * 2 + 1] = sqrtf(s_part[t][2] + s_part[t][3]);
    }
}

// ---------------------------------------------------------------------------
// ysum: Y[bin,h,:] = sum_{n in bin} mag[n,h] * x[n,:]; S[bin,h] = sum mag
// One block per bin, 512 threads, half2-vectorized.
// ---------------------------------------------------------------------------
__global__ void ysum_kernel()
{
    __shared__ float sm[9 * 16];
    const int m = blockIdx.x;            // b*512 + g
    const int b = m >> 9, g = m & 511;
    const int t = threadIdx.x;

    int n = (int)(((long long)g * 4095) / 511) - 2;
    if (n < 0) n = 0;
    while (bin_of(n) < g) ++n;
    const int ns = n;
    int ne = n;
    while (ne < NN && bin_of(ne) == g) ++ne;
    const int cnt = ne - ns;             // 1..9

    if (t < cnt * 16)
        sm[t] = g_mag[((size_t)(b * NN + ns + (t >> 4))) * HH + (t & 15)];
    __syncthreads();

    const __half2* X2 = reinterpret_cast<const __half2*>(g_x);
    __half2* Y2 = reinterpret_cast<__half2*>(g_Y);
    float2 xf[9];
    for (int i = 0; i < cnt; ++i)
        xf[i] = __half22float2(X2[(((size_t)(b * NN + ns + i)) << 9) + t]);
    for (int h = 0; h < 16; ++h) {
        float2 s = make_float2(0.f, 0.f);
        for (int i = 0; i < cnt; ++i) {
            float wgt = sm[i * 16 + h];
            s.x = fmaf(wgt, xf[i].x, s.x);
            s.y = fmaf(wgt, xf[i].y, s.y);
        }
        Y2[(((size_t)m * HH + h) << 9) + t] = __floats2half2_rn(s.x, s.y);
    }
    if (t < 16) {
        float s = 0.f;
        for (int i = 0; i < cnt; ++i) s += sm[i * 16 + t];
        g_S[(size_t)m * HH + t] = s;
    }
}

// ---------------------------------------------------------------------------
// GEMM #2: field[bin,h,:] = Y[bin,h,:] @ vw_h^T + S*vb_h
// Block 64 bins x 64 cols, 4 warps (32x32 tiles), 3-stage x16KB, 4 CTAs/SM.
// ---------------------------------------------------------------------------
#define FSTAGE 16384
__global__ __launch_bounds__(128, 4) void f_gemm_kernel(const float* __restrict__ vb)
{
    extern __shared__ char sp[];
    __shared__ float s_vb[64], s_S[64];
    const int t    = threadIdx.x;
    const int lane = t & 31;
    const int w    = t >> 5;
    const int m0w  = (w >> 1) * 32;
    const int n0w  = (w & 1) * 32;
    const int m0   = blockIdx.x * 64;     // bins (b*512+g)
    const int h    = blockIdx.y;
    uint32_t sb = smem_u32(sp);

    if (t < 64)       s_vb[t]      = vb[h * 64 + t];
    else if (t < 128) s_S[t - 64]  = g_S[(size_t)(m0 + t - 64) * HH + h];

    float acc[2][4][4];
    #pragma unroll
    for (int a = 0; a < 2; ++a)
        #pragma unroll
        for (int b = 0; b < 4; ++b)
            #pragma unroll
            for (int q = 0; q < 4; ++q) acc[a][b][q] = 0.f;

    const __half* Abase = g_Y  + ((size_t)m0 * HH + h) * DD;
    const __half* Bbase = g_vw + (size_t)(h * 64) * DD;
    const size_t strA = (size_t)HH * DD;  // 16384

    load_tiles<128,64,64,8192>(Abase,      strA, Bbase,      DD, sb,          t); CP_COMMIT();
    load_tiles<128,64,64,8192>(Abase + KC, strA, Bbase + KC, DD, sb + FSTAGE, t); CP_COMMIT();

    for (int s = 0; s < NCH; ++s) {
        if (s + 2 < NCH) { CP_WAIT1(); } else { CP_WAIT0(); }
        __syncthreads();
        if (s + 2 < NCH) {
            load_tiles<128,64,64,8192>(Abase + (s + 2) * KC, strA, Bbase + (s + 2) * KC, DD,
                                       sb + ((s + 2) % 3) * FSTAGE, t);
            CP_COMMIT();
        }
        compute32x32(sb + (s % 3) * FSTAGE, m0w, n0w, lane, acc);
    }

    #pragma unroll
    for (int mt = 0; mt < 2; ++mt)
        #pragma unroll
        for (int half = 0; half < 2; ++half) {
            int mloc = m0w + mt * 16 + half * 8 + (lane >> 2);
            int m = m0 + mloc;
            int b = m >> 9, g = m & 511;
            float Sv = s_S[mloc];
            float* dst = g_field + ((((size_t)(b * HH + h)) * GG + g) << 6);
            #pragma unroll
            for (int nt = 0; nt < 4; ++nt) {
                int cl = n0w + nt * 8 + ((lane & 3) << 1);
                float2 o;
                o.x = acc[mt][nt][half * 2 + 0] + Sv * s_vb[cl];
                o.y = acc[mt][nt][half * 2 + 1] + Sv * s_vb[cl + 1];
                *reinterpret_cast<float2*>(dst + cl) = o;
            }
        }
}

// ---------------------------------------------------------------------------
// circular exp-kernel convolution; writes out-GEMM A matrix (fp16) directly
// ---------------------------------------------------------------------------
#define TAPS 144
__global__ void conv_kernel()
{
    extern __shared__ float sf[];
    __shared__ float wsh[TAPS];
    int bh = blockIdx.x;
    int b  = bh >> 4, h = bh & 15;
    const float* F = g_field + (size_t)bh * GG * HDIM;
    for (int i = threadIdx.x; i < GG * HDIM; i += blockDim.x)
        sf[i] = F[i];
    if (threadIdx.x < TAPS) {
        float Z = 0.f;
        for (int dd = 256; dd >= 1; --dd) Z += expf(-(float)dd / 3.0f);
        Z += 1e-8f;
        wsh[threadIdx.x] = expf(-(float)(threadIdx.x + 1) / 3.0f) / Z;
    }
    __syncthreads();

    int d    = threadIdx.x & 63;
    int g0   = (threadIdx.x >> 6) * 64;
    int gtop = g0 + 63;

    float acc = 0.f;
    for (int j = TAPS - 1; j >= 0; --j)
        acc = fmaf(wsh[j], sf[((gtop + 257 + j) & 511) * HDIM + d], acc);

    __half* outA = g_A + ((size_t)b * GG << 10) + h * 64 + d;
    outA[(size_t)gtop << 10] = __float2half(acc);

    const float a  = 0.7165313105737893f;
    const float w0 = wsh[0];
    float C = acc;
    for (int g = gtop - 1; g >= g0; --g) {
        C = fmaf(a, C, w0 * sf[((g + 257) & 511) * HDIM + d]);
        outA[(size_t)g << 10] = __float2half(C);
    }
}

// ---------------------------------------------------------------------------
// GEMM #3: out rows = A @ ow^T + ob, scattered to all tokens per bin.
// Block 64 bins x 64 cols, 4 warps (32x32), 3-stage x16KB, 4 CTAs/SM.
// ---------------------------------------------------------------------------
__global__ __launch_bounds__(128, 4) void out_gemm_kernel(
    const float* __restrict__ ob, float* __restrict__ out)
{
    extern __shared__ char sp[];
    __shared__ float s_ob[64];
    const int t    = threadIdx.x;
    const int lane = t & 31;
    const int w    = t >> 5;
    const int m0w  = (w >> 1) * 32;
    const int n0w  = (w & 1) * 32;
    const int m0   = blockIdx.x * 64;     // rows m = b*512 + g
    const int j0   = blockIdx.y * 64;
    uint32_t sb = smem_u32(sp);

    if (t < 64) s_ob[t] = ob[j0 + t];

    float acc[2][4][4];
    #pragma unroll
    for (int a = 0; a < 2; ++a)
        #pragma unroll
        for (int b = 0; b < 4; ++b)
            #pragma unroll
            for (int q = 0; q < 4; ++q) acc[a][b][q] = 0.f;

    const __half* Abase = g_A  + (size_t)m0 * DD;
    const __half* Bbase = g_ow + (size_t)j0 * DD;

    load_tiles<128,64,64,8192>(Abase,      DD, Bbase,      DD, sb,          t); CP_COMMIT();
    load_tiles<128,64,64,8192>(Abase + KC, DD, Bbase + KC, DD, sb + FSTAGE, t); CP_COMMIT();

    for (int s = 0; s < NCH; ++s) {
        if (s + 2 < NCH) { CP_WAIT1(); } else { CP_WAIT0(); }
        __syncthreads();
        if (s + 2 < NCH) {
            load_tiles<128,64,64,8192>(Abase + (s + 2) * KC, DD, Bbase + (s + 2) * KC, DD,
                                       sb + ((s + 2) % 3) * FSTAGE, t);
            CP_COMMIT();
        }
        compute32x32(sb + (s % 3) * FSTAGE, m0w, n0w, lane, acc);
    }

    // scatter each bin-row to every token n with bin_of(n) == g
    const int b = m0 >> 9;
    #pragma unroll
    for (int mt = 0; mt < 2; ++mt) {
        #pragma unroll
        for (int half = 0; half < 2; ++half) {
            int m = m0 + m0w + mt * 16 + (lane >> 2) + half * 8;
            int g = m & 511;
            int n = (int)(((long long)g * 4095) / 511) - 2;
            if (n < 0) n = 0;
            while (bin_of(n) < g) ++n;
            for (; n < NN && bin_of(n) == g; ++n) {
                float* dst = out + (((size_t)(b * NN + n)) << 10) + j0;
                #pragma unroll
                for (int nt = 0; nt < 4; ++nt) {
                    int cl = n0w + nt * 8 + ((lane & 3) << 1);
                    float2 o;
                    o.x = acc[mt][nt][half * 2 + 0] + s_ob[cl];
                    o.y = acc[mt][nt][half * 2 + 1] + s_ob[cl + 1];
                    *reinterpret_cast<float2*>(dst + cl) = o;
                }
            }
        }
    }
}

// ---------------------------------------------------------------------------
extern "C" void kernel_launch(void* const* d_in, const int* in_sizes, int n_in,
                              void* d_out, int out_size)
{
    const float* x  = (const float*)d_in[0];
    // d_in[1], d_in[2] are q_w, q_b — unused by the reference output.
    const float* kw = (const float*)d_in[3];
    const float* kb = (const float*)d_in[4];
    const float* vw = (const float*)d_in[5];
    const float* vb = (const float*)d_in[6];
    const float* ow = (const float*)d_in[7];
    const float* ob = (const float*)d_in[8];
    float* out = (float*)d_out;

    cudaFuncSetAttribute(k_gemm_kernel,   cudaFuncAttributeMaxDynamicSharedMemorySize, 3 * KSTAGE);
    cudaFuncSetAttribute(f_gemm_kernel,   cudaFuncAttributeMaxDynamicSharedMemorySize, 3 * FSTAGE);
    cudaFuncSetAttribute(out_gemm_kernel, cudaFuncAttributeMaxDynamicSharedMemorySize, 3 * FSTAGE);
    cudaFuncSetAttribute(conv_kernel, cudaFuncAttributeMaxDynamicSharedMemorySize,
                         GG * HDIM * (int)sizeof(float));

    prep_kernel<<<19456, 256>>>(x, kw, vw, ow);

    k_gemm_kernel<<<dim3(BNTOK / 128, 8), 256, 3 * KSTAGE>>>(kb);

    ysum_kernel<<<BB * GG, 512>>>();

    f_gemm_kernel<<<dim3((BB * GG) / 64, HH), 128, 3 * FSTAGE>>>(vb);

    conv_kernel<<<BB * HH, 512, GG * HDIM * sizeof(float)>>>();

    out_gemm_kernel<<<dim3((BB * GG) / 64, DD / 64), 128, 3 * FSTAGE>>>(ob, out);
}

// round 14
// speedup vs baseline: 1.2068x; 1.0005x over previous
#include <cuda_runtime.h>
#include <cuda_fp16.h>
#include <math.h>
#include <stdint.h>

#define BB 4
#define NN 4096
#define DD 1024
#define HH 16
#define HDIM 64
#define GG 512
#define BNTOK (BB*NN)

// ---------------- scratch (device globals; no allocations allowed) ----------
__device__ float  g_field[(size_t)BB * HH * GG * HDIM]; // 8MB
__device__ float  g_mag [(size_t)BNTOK * HH];           // 1MB  ||k|| per (token, head)
__device__ float  g_S   [(size_t)BB * GG * HH];         // 128KB sum of mags per (bin, head)
__device__ __half g_x   [(size_t)BNTOK * DD];           // 32MB fp16 x
__device__ __half g_kw  [(size_t)DD * DD];              // 2MB
__device__ __half g_vw  [(size_t)DD * DD];              // 2MB
__device__ __half g_ow  [(size_t)DD * DD];              // 2MB
__device__ __half g_Y   [(size_t)BB * GG * HH * DD];    // 64MB weighted segsum of x
__device__ __half g_A   [(size_t)BB * GG * DD];         // 4MB  conv result, repacked

// Replicates jnp: pos = (n/4095.0f)*511.0f ; int32 trunc ; clip
__device__ __forceinline__ int bin_of(int n) {
    float p = ((float)n / 4095.0f) * 511.0f;
    int g = (int)p;
    g = g < 0 ? 0 : g;
    return g > 511 ? 511 : g;
}

// ---------------- baseline-PTX tensor helpers (sm_80+, ok on compute_103) ---
__device__ __forceinline__ uint32_t smem_u32(const void* p) {
    uint32_t a;
    asm("{ .reg .u64 t; cvta.to.shared.u64 t, %1; cvt.u32.u64 %0, t; }" : "=r"(a) : "l"(p));
    return a;
}
__device__ __forceinline__ void ldmx4(uint32_t* r, uint32_t a) {
    asm volatile("ldmatrix.sync.aligned.m8n8.x4.shared.b16 {%0,%1,%2,%3}, [%4];"
        : "=r"(r[0]), "=r"(r[1]), "=r"(r[2]), "=r"(r[3]) : "r"(a));
}
__device__ __forceinline__ void mma16816(float* c, const uint32_t* a, const uint32_t* b) {
    asm volatile("mma.sync.aligned.m16n8k16.row.col.f32.f16.f16.f32 "
        "{%0,%1,%2,%3}, {%4,%5,%6,%7}, {%8,%9}, {%0,%1,%2,%3};"
        : "+f"(c[0]), "+f"(c[1]), "+f"(c[2]), "+f"(c[3])
        : "r"(a[0]), "r"(a[1]), "r"(a[2]), "r"(a[3]), "r"(b[0]), "r"(b[1]));
}
#define CP_ASYNC(d, s) asm volatile("cp.async.cg.shared.global [%0], [%1], 16;" :: "r"(d), "l"(s) : "memory")
#define CP_COMMIT()    asm volatile("cp.async.commit_group;" ::: "memory")
#define CP_WAIT1()     asm volatile("cp.async.wait_group 1;" ::: "memory")
#define CP_WAIT0()     asm volatile("cp.async.wait_group 0;" ::: "memory")

#define KC    64
#define NCH   16                  // 1024 / 64

// swizzled byte offset for (row, 16B-chunk c in 0..7)
__device__ __forceinline__ uint32_t swz(uint32_t row, uint32_t c) {
    return row * 128u + ((c ^ (row & 7u)) << 4);
}

// generic tile loader: gA/gB pre-offset to (row0, kc*KC). BOFF = AROWS*128.
template <int NTHR, int AROWS, int BROWS, int BOFF>
__device__ __forceinline__ void load_tiles(
    const __half* __restrict__ gA, size_t strideA,
    const __half* __restrict__ gB, size_t strideB,
    uint32_t sbase, int t)
{
    #pragma unroll
    for (int i = 0; i < AROWS * 8 / NTHR; ++i) {
        int e = t + i * NTHR;
        int row = e >> 3, c = e & 7;
        CP_ASYNC(sbase + swz(row, c), gA + (size_t)row * strideA + c * 8);
    }
    #pragma unroll
    for (int i = 0; i < BROWS * 8 / NTHR; ++i) {
        int e = t + i * NTHR;
        int row = e >> 3, c = e & 7;
        CP_ASYNC(sbase + BOFF + swz(row, c), gB + (size_t)row * strideB + c * 8);
    }
}

// 32x64 warp-tile compute over one KC=64 stage (A tile 64 rows; BOFF 8192)
__device__ __forceinline__ void compute32x64(uint32_t st, int m0w, int n0w, int lane,
                                             float acc[2][8][4])
{
    #pragma unroll
    for (int kh = 0; kh < 4; ++kh) {
        uint32_t ah[2][4];
        uint32_t arow = (uint32_t)(m0w + (lane & 15));
        uint32_t ac   = (uint32_t)(kh * 2 + (lane >> 4));
        #pragma unroll
        for (int mt = 0; mt < 2; ++mt)
            ldmx4(ah[mt], st + swz(arow + mt * 16, ac));
        uint32_t bh[4][4];
        uint32_t brow = (uint32_t)(n0w + (lane & 7) + ((lane >> 4) << 3));
        uint32_t bc   = (uint32_t)(kh * 2 + ((lane & 8) >> 3));
        #pragma unroll
        for (int bj = 0; bj < 4; ++bj)
            ldmx4(bh[bj], st + 8192 + swz(brow + bj * 16, bc));
        #pragma unroll
        for (int mt = 0; mt < 2; ++mt)
            #pragma unroll
            for (int nt = 0; nt < 8; ++nt)
                mma16816(acc[mt][nt], ah[mt], &bh[nt >> 1][(nt & 1) * 2]);
    }
}

// 32x32 warp-tile compute over one KC=64 stage (A tile 64 rows; BOFF 8192)
__device__ __forceinline__ void compute32x32(uint32_t st, int m0w, int n0w, int lane,
                                             float acc[2][4][4])
{
    #pragma unroll
    for (int kh = 0; kh < 4; ++kh) {
        uint32_t ah[2][4];
        uint32_t arow = (uint32_t)(m0w + (lane & 15));
        uint32_t ac   = (uint32_t)(kh * 2 + (lane >> 4));
        #pragma unroll
        for (int mt = 0; mt < 2; ++mt)
            ldmx4(ah[mt], st + swz(arow + mt * 16, ac));
        uint32_t bh[2][4];
        uint32_t brow = (uint32_t)(n0w + (lane & 7) + ((lane >> 4) << 3));
        uint32_t bc   = (uint32_t)(kh * 2 + ((lane & 8) >> 3));
        #pragma unroll
        for (int bj = 0; bj < 2; ++bj)
            ldmx4(bh[bj], st + 8192 + swz(brow + bj * 16, bc));
        #pragma unroll
        for (int mt = 0; mt < 2; ++mt)
            #pragma unroll
            for (int nt = 0; nt < 4; ++nt)
                mma16816(acc[mt][nt], ah[mt], &bh[nt >> 1][(nt & 1) * 2]);
    }
}

// ---------------------------------------------------------------------------
// prep: all fp32->fp16 conversions merged in one launch
// ---------------------------------------------------------------------------
__global__ void prep_kernel(const float* __restrict__ x,  const float* __restrict__ kw,
                            const float* __restrict__ vw, const float* __restrict__ ow)
{
    int bid = blockIdx.x;
    const float* src; __half2* dst; size_t i;
    if (bid < 16384)      { src = x;  dst = (__half2*)g_x;  i = (size_t)bid * 256 + threadIdx.x; }
    else if (bid < 17408) { src = kw; dst = (__half2*)g_kw; i = (size_t)(bid - 16384) * 256 + threadIdx.x; }
    else if (bid < 18432) { src = vw; dst = (__half2*)g_vw; i = (size_t)(bid - 17408) * 256 + threadIdx.x; }
    else                  { src = ow; dst = (__half2*)g_ow; i = (size_t)(bid - 18432) * 256 + threadIdx.x; }
    float4 v = reinterpret_cast<const float4*>(src)[i];
    dst[2*i]   = __half2(__float2half(v.x), __float2half(v.y));
    dst[2*i+1] = __half2(__float2half(v.z), __float2half(v.w));
}

// ---------------------------------------------------------------------------
// GEMM #1 (k only): K = x @ kw^T, fused ||k+kb|| -> g_mag.
// Block 64 tokens x 128 cols (2 heads). 4 warps (2x2), warp tile 32x64,
// 2-stage x24KB = 48KB -> 4 CTAs/SM (16 warps/SM = 4 per SMSP).
// Each warp's 64 n-cols = exactly one head -> warp-local ||k|| reduction.
// ---------------------------------------------------------------------------
#define KSTAGE 24576
__global__ __launch_bounds__(128, 4) void k_gemm_kernel(const float* __restrict__ kb)
{
    extern __shared__ char sp[];
    __shared__ float s_kb[128];
    const int t    = threadIdx.x;
    const int lane = t & 31;
    const int w    = t >> 5;              // 0..3
    const int m0w  = (w >> 1) * 32;
    const int n0w  = (w & 1) * 64;
    const int m0   = blockIdx.x * 64;
    const int pair = blockIdx.y;          // heads 2*pair, 2*pair+1
    const int n0   = pair * 128;
    uint32_t sb = smem_u32(sp);

    if (t < 128) s_kb[t] = kb[pair * 128 + t];

    float acc[2][8][4];
    #pragma unroll
    for (int a = 0; a < 2; ++a)
        #pragma unroll
        for (int b = 0; b < 8; ++b)
            #pragma unroll
            for (int q = 0; q < 4; ++q) acc[a][b][q] = 0.f;

    const __half* Abase = g_x  + (size_t)m0 * DD;
    const __half* Bbase = g_kw + (size_t)n0 * DD;

    load_tiles<128,64,128,8192>(Abase, DD, Bbase, DD, sb, t); CP_COMMIT();

    for (int s = 0; s < NCH; ++s) {
        if (s + 1 < NCH) {
            load_tiles<128,64,128,8192>(Abase + (s + 1) * KC, DD, Bbase + (s + 1) * KC, DD,
                                        sb + ((s + 1) & 1) * KSTAGE, t);
            CP_COMMIT(); CP_WAIT1();
        } else { CP_WAIT0(); }
        __syncthreads();
        compute32x64(sb + (s & 1) * KSTAGE, m0w, n0w, lane, acc);
        __syncthreads();
    }

    // epilogue: warp-local ||k|| per row (this warp's 64 cols = one full head)
    const int head = pair * 2 + (n0w >> 6);
    #pragma unroll
    for (int mt = 0; mt < 2; ++mt)
        #pragma unroll
        for (int half = 0; half < 2; ++half) {
            float ssq = 0.f;
            #pragma unroll
            for (int nt = 0; nt < 8; ++nt) {
                int cl = n0w + nt * 8 + ((lane & 3) << 1);
                float k0 = acc[mt][nt][half * 2 + 0] + s_kb[cl];
                float k1 = acc[mt][nt][half * 2 + 1] + s_kb[cl + 1];
                ssq = fmaf(k0, k0, fmaf(k1, k1, ssq));
            }
            ssq += __shfl_xor_sync(0xFFFFFFFF, ssq, 1);
            ssq += __shfl_xor_sync(0xFFFFFFFF, ssq, 2);
            if ((lane & 3) == 0) {
                int tok = m0 + m0w + mt * 16 + half * 8 + (lane >> 2);
                g_mag[(size_t)tok * HH + head] = sqrtf(ssq);
            }
        }
}

// ---------------------------------------------------------------------------
// ysum: Y[bin,h,:] = sum_{n in bin} mag[n,h] * x[n,:]; S[bin,h] = sum mag
// One block per bin, 512 threads, half2-vectorized.
// ---------------------------------------------------------------------------
__global__ void ysum_kernel()
{
    __shared__ float sm[9 * 16];
    const int m = blockIdx.x;            // b*512 + g
    const int b = m >> 9, g = m & 511;
    const int t = threadIdx.x;

    int n = (int)(((long long)g * 4095) / 511) - 2;
    if (n < 0) n = 0;
    while (bin_of(n) < g) ++n;
    const int ns = n;
    int ne = n;
    while (ne < NN && bin_of(ne) == g) ++ne;
    const int cnt = ne - ns;             // 1..9

    if (t < cnt * 16)
        sm[t] = g_mag[((size_t)(b * NN + ns + (t >> 4))) * HH + (t & 15)];
    __syncthreads();

    const __half2* X2 = reinterpret_cast<const __half2*>(g_x);
    __half2* Y2 = reinterpret_cast<__half2*>(g_Y);
    float2 xf[9];
    for (int i = 0; i < cnt; ++i)
        xf[i] = __half22float2(X2[(((size_t)(b * NN + ns + i)) << 9) + t]);
    for (int h = 0; h < 16; ++h) {
        float2 s = make_float2(0.f, 0.f);
        for (int i = 0; i < cnt; ++i) {
            float wgt = sm[i * 16 + h];
            s.x = fmaf(wgt, xf[i].x, s.x);
            s.y = fmaf(wgt, xf[i].y, s.y);
        }
        Y2[(((size_t)m * HH + h) << 9) + t] = __floats2half2_rn(s.x, s.y);
    }
    if (t < 16) {
        float s = 0.f;
        for (int i = 0; i < cnt; ++i) s += sm[i * 16 + t];
        g_S[(size_t)m * HH + t] = s;
    }
}

// ---------------------------------------------------------------------------
// GEMM #2: field[bin,h,:] = Y[bin,h,:] @ vw_h^T + S*vb_h
// Block 64 bins x 64 cols, 4 warps (32x32 tiles), 3-stage x16KB, 4 CTAs/SM.
// ---------------------------------------------------------------------------
#define FSTAGE 16384
__global__ __launch_bounds__(128, 4) void f_gemm_kernel(const float* __restrict__ vb)
{
    extern __shared__ char sp[];
    __shared__ float s_vb[64], s_S[64];
    const int t    = threadIdx.x;
    const int lane = t & 31;
    const int w    = t >> 5;
    const int m0w  = (w >> 1) * 32;
    const int n0w  = (w & 1) * 32;
    const int m0   = blockIdx.x * 64;     // bins (b*512+g)
    const int h    = blockIdx.y;
    uint32_t sb = smem_u32(sp);

    if (t < 64)       s_vb[t]      = vb[h * 64 + t];
    else if (t < 128) s_S[t - 64]  = g_S[(size_t)(m0 + t - 64) * HH + h];

    float acc[2][4][4];
    #pragma unroll
    for (int a = 0; a < 2; ++a)
        #pragma unroll
        for (int b = 0; b < 4; ++b)
            #pragma unroll
            for (int q = 0; q < 4; ++q) acc[a][b][q] = 0.f;

    const __half* Abase = g_Y  + ((size_t)m0 * HH + h) * DD;
    const __half* Bbase = g_vw + (size_t)(h * 64) * DD;
    const size_t strA = (size_t)HH * DD;  // 16384

    load_tiles<128,64,64,8192>(Abase,      strA, Bbase,      DD, sb,          t); CP_COMMIT();
    load_tiles<128,64,64,8192>(Abase + KC, strA, Bbase + KC, DD, sb + FSTAGE, t); CP_COMMIT();

    for (int s = 0; s < NCH; ++s) {
        if (s + 2 < NCH) { CP_WAIT1(); } else { CP_WAIT0(); }
        __syncthreads();
        if (s + 2 < NCH) {
            load_tiles<128,64,64,8192>(Abase + (s + 2) * KC, strA, Bbase + (s + 2) * KC, DD,
                                       sb + ((s + 2) % 3) * FSTAGE, t);
            CP_COMMIT();
        }
        compute32x32(sb + (s % 3) * FSTAGE, m0w, n0w, lane, acc);
    }

    #pragma unroll
    for (int mt = 0; mt < 2; ++mt)
        #pragma unroll
        for (int half = 0; half < 2; ++half) {
            int mloc = m0w + mt * 16 + half * 8 + (lane >> 2);
            int m = m0 + mloc;
            int b = m >> 9, g = m & 511;
            float Sv = s_S[mloc];
            float* dst = g_field + ((((size_t)(b * HH + h)) * GG + g) << 6);
            #pragma unroll
            for (int nt = 0; nt < 4; ++nt) {
                int cl = n0w + nt * 8 + ((lane & 3) << 1);
                float2 o;
                o.x = acc[mt][nt][half * 2 + 0] + Sv * s_vb[cl];
                o.y = acc[mt][nt][half * 2 + 1] + Sv * s_vb[cl + 1];
                *reinterpret_cast<float2*>(dst + cl) = o;
            }
        }
}

// ---------------------------------------------------------------------------
// circular exp-kernel convolution; writes out-GEMM A matrix (fp16) directly
// ---------------------------------------------------------------------------
#define TAPS 144
__global__ void conv_kernel()
{
    extern __shared__ float sf[];
    __shared__ float wsh[TAPS];
    int bh = blockIdx.x;
    int b  = bh >> 4, h = bh & 15;
    const float* F = g_field + (size_t)bh * GG * HDIM;
    for (int i = threadIdx.x; i < GG * HDIM; i += blockDim.x)
        sf[i] = F[i];
    if (threadIdx.x < TAPS) {
        float Z = 0.f;
        for (int dd = 256; dd >= 1; --dd) Z += expf(-(float)dd / 3.0f);
        Z += 1e-8f;
        wsh[threadIdx.x] = expf(-(float)(threadIdx.x + 1) / 3.0f) / Z;
    }
    __syncthreads();

    int d    = threadIdx.x & 63;
    int g0   = (threadIdx.x >> 6) * 64;
    int gtop = g0 + 63;

    float acc = 0.f;
    for (int j = TAPS - 1; j >= 0; --j)
        acc = fmaf(wsh[j], sf[((gtop + 257 + j) & 511) * HDIM + d], acc);

    __half* outA = g_A + ((size_t)b * GG << 10) + h * 64 + d;
    outA[(size_t)gtop << 10] = __float2half(acc);

    const float a  = 0.7165313105737893f;
    const float w0 = wsh[0];
    float C = acc;
    for (int g = gtop - 1; g >= g0; --g) {
        C = fmaf(a, C, w0 * sf[((g + 257) & 511) * HDIM + d]);
        outA[(size_t)g << 10] = __float2half(C);
    }
}

// ---------------------------------------------------------------------------
// GEMM #3: out rows = A @ ow^T + ob, scattered to all tokens per bin.
// Block 64 bins x 64 cols, 4 warps (32x32), 3-stage x16KB, 4 CTAs/SM.
// ---------------------------------------------------------------------------
__global__ __launch_bounds__(128, 4) void out_gemm_kernel(
    const float* __restrict__ ob, float* __restrict__ out)
{
    extern __shared__ char sp[];
    __shared__ float s_ob[64];
    const int t    = threadIdx.x;
    const int lane = t & 31;
    const int w    = t >> 5;
    const int m0w  = (w >> 1) * 32;
    const int n0w  = (w & 1) * 32;
    const int m0   = blockIdx.x * 64;     // rows m = b*512 + g
    const int j0   = blockIdx.y * 64;
    uint32_t sb = smem_u32(sp);

    if (t < 64) s_ob[t] = ob[j0 + t];

    float acc[2][4][4];
    #pragma unroll
    for (int a = 0; a < 2; ++a)
        #pragma unroll
        for (int b = 0; b < 4; ++b)
            #pragma unroll
            for (int q = 0; q < 4; ++q) acc[a][b][q] = 0.f;

    const __half* Abase = g_A  + (size_t)m0 * DD;
    const __half* Bbase = g_ow + (size_t)j0 * DD;

    load_tiles<128,64,64,8192>(Abase,      DD, Bbase,      DD, sb,          t); CP_COMMIT();
    load_tiles<128,64,64,8192>(Abase + KC, DD, Bbase + KC, DD, sb + FSTAGE, t); CP_COMMIT();

    for (int s = 0; s < NCH; ++s) {
        if (s + 2 < NCH) { CP_WAIT1(); } else { CP_WAIT0(); }
        __syncthreads();
        if (s + 2 < NCH) {
            load_tiles<128,64,64,8192>(Abase + (s + 2) * KC, DD, Bbase + (s + 2) * KC, DD,
                                       sb + ((s + 2) % 3) * FSTAGE, t);
            CP_COMMIT();
        }
        compute32x32(sb + (s % 3) * FSTAGE, m0w, n0w, lane, acc);
    }

    // scatter each bin-row to every token n with bin_of(n) == g
    const int b = m0 >> 9;
    #pragma unroll
    for (int mt = 0; mt < 2; ++mt) {
        #pragma unroll
        for (int half = 0; half < 2; ++half) {
            int m = m0 + m0w + mt * 16 + (lane >> 2) + half * 8;
            int g = m & 511;
            int n = (int)(((long long)g * 4095) / 511) - 2;
            if (n < 0) n = 0;
            while (bin_of(n) < g) ++n;
            for (; n < NN && bin_of(n) == g; ++n) {
                float* dst = out + (((size_t)(b * NN + n)) << 10) + j0;
                #pragma unroll
                for (int nt = 0; nt < 4; ++nt) {
                    int cl = n0w + nt * 8 + ((lane & 3) << 1);
                    float2 o;
                    o.x = acc[mt][nt][half * 2 + 0] + s_ob[cl];
                    o.y = acc[mt][nt][half * 2 + 1] + s_ob[cl + 1];
                    *reinterpret_cast<float2*>(dst + cl) = o;
                }
            }
        }
    }
}

// ---------------------------------------------------------------------------
extern "C" void kernel_launch(void* const* d_in, const int* in_sizes, int n_in,
                              void* d_out, int out_size)
{
    const float* x  = (const float*)d_in[0];
    // d_in[1], d_in[2] are q_w, q_b — unused by the reference output.
    const float* kw = (const float*)d_in[3];
    const float* kb = (const float*)d_in[4];
    const float* vw = (const float*)d_in[5];
    const float* vb = (const float*)d_in[6];
    const float* ow = (const float*)d_in[7];
    const float* ob = (const float*)d_in[8];
    float* out = (float*)d_out;

    cudaFuncSetAttribute(k_gemm_kernel,   cudaFuncAttributeMaxDynamicSharedMemorySize, 2 * KSTAGE);
    cudaFuncSetAttribute(f_gemm_kernel,   cudaFuncAttributeMaxDynamicSharedMemorySize, 3 * FSTAGE);
    cudaFuncSetAttribute(out_gemm_kernel, cudaFuncAttributeMaxDynamicSharedMemorySize, 3 * FSTAGE);
    cudaFuncSetAttribute(conv_kernel, cudaFuncAttributeMaxDynamicSharedMemorySize,
                         GG * HDIM * (int)sizeof(float));

    prep_kernel<<<19456, 256>>>(x, kw, vw, ow);

    k_gemm_kernel<<<dim3(BNTOK / 64, 8), 128, 2 * KSTAGE>>>(kb);

    ysum_kernel<<<BB * GG, 512>>>();

    f_gemm_kernel<<<dim3((BB * GG) / 64, HH), 128, 3 * FSTAGE>>>(vb);

    conv_kernel<<<BB * HH, 512, GG * HDIM * sizeof(float)>>>();

    out_gemm_kernel<<<dim3((BB * GG) / 64, DD / 64), 128, 3 * FSTAGE>>>(ob, out);
}